// round 4
// baseline (speedup 1.0000x reference)
#include <cuda_runtime.h>
#include <cuda_bf16.h>
#include <math.h>

#define N_NODES 50000
#define N_EDGES 500000
#define IN_CH   128
#define OUT_CH  256

// Scratch (device globals — no allocation allowed)
__device__ float g_agg[N_NODES * IN_CH];   // Â·x  (25.6 MB)
__device__ float g_deg[N_NODES];
__device__ float g_dinv[N_NODES];
__device__ float g_ew[N_EDGES];

// ---------------------------------------------------------------------------
// 1. init degree with self-loop weight 1
__global__ void k_init_deg() {
    int i = blockIdx.x * blockDim.x + threadIdx.x;
    if (i < N_NODES) g_deg[i] = 1.0f;
}

// 2. sigmoid(edge_weight), accumulate degree on target node
//    edge_index is int32 (JAX default x64-disabled downcasts int64 -> int32).
__global__ void k_edge_deg(const int* __restrict__ ei,
                           const float* __restrict__ w) {
    int e = blockIdx.x * blockDim.x + threadIdx.x;
    if (e < N_EDGES) {
        float s = 1.0f / (1.0f + expf(-w[e]));
        g_ew[e] = s;
        int col = ei[N_EDGES + e];
        if ((unsigned)col < N_NODES)
            atomicAdd(&g_deg[col], s);
    }
}

// 3. dinv = rsqrt(deg)   (deg >= 1 always since self-loop weight 1)
__global__ void k_dinv() {
    int i = blockIdx.x * blockDim.x + threadIdx.x;
    if (i < N_NODES) g_dinv[i] = rsqrtf(g_deg[i]);
}

// 4. self-loop contribution: agg[i] = x[i] * dinv[i]^2   (32 threads/node, float4)
__global__ void k_selfloop(const float* __restrict__ x) {
    int t = blockIdx.x * blockDim.x + threadIdx.x;
    int i = t >> 5;
    int c = (t & 31) << 2;
    if (i < N_NODES) {
        float di = g_dinv[i];
        float s = di * di;
        float4 v = *(const float4*)(x + i * IN_CH + c);
        v.x *= s; v.y *= s; v.z *= s; v.w *= s;
        *(float4*)(g_agg + i * IN_CH + c) = v;
    }
}

// 5. edge scatter: agg[col] += x[row] * (dinv[row]*ew*dinv[col])
//    32 threads per edge; each lane handles 4 channels (float4 gather,
//    4 scalar atomicAdds -> RED.E.ADD.F32, fire-and-forget).
__global__ void k_scatter(const int* __restrict__ ei,
                          const float* __restrict__ x) {
    int t = blockIdx.x * blockDim.x + threadIdx.x;
    int e = t >> 5;
    if (e >= N_EDGES) return;
    int c = (t & 31) << 2;
    int row = ei[e];
    int col = ei[N_EDGES + e];
    if ((unsigned)row >= N_NODES || (unsigned)col >= N_NODES) return;
    float norm = g_dinv[row] * g_ew[e] * g_dinv[col];
    float4 v = *(const float4*)(x + row * IN_CH + c);
    float* dst = g_agg + col * IN_CH + c;
    atomicAdd(dst + 0, v.x * norm);
    atomicAdd(dst + 1, v.y * norm);
    atomicAdd(dst + 2, v.z * norm);
    atomicAdd(dst + 3, v.w * norm);
}

// 6. GEMM: out[N_NODES, OUT_CH] = agg[N_NODES, IN_CH] @ W[IN_CH, OUT_CH] + b
//    64x64 block tile, BK=16, 256 threads, 4x4 microtile.
#define BM 64
#define BN 64
#define BK 16

__global__ __launch_bounds__(256) void k_gemm(const float* __restrict__ W,
                                              const float* __restrict__ bias,
                                              float* __restrict__ out) {
    __shared__ __align__(16) float As[BK][BM + 4];
    __shared__ __align__(16) float Bs[BK][BN];

    int tid = threadIdx.x;
    int bm = blockIdx.y * BM;
    int bn = blockIdx.x * BN;
    int tx = tid & 15;        // 0..15 -> 4 output cols each
    int ty = tid >> 4;        // 0..15 -> 4 output rows each

    // A-tile load mapping: each thread loads one float4 of a row
    int ar = tid >> 2;          // 0..63  (row within tile)
    int ac = (tid & 3) << 2;    // 0,4,8,12 (k offset within BK)
    // B-tile load mapping
    int br = tid >> 4;          // 0..15 (k row)
    int bc = (tid & 15) << 2;   // col offset

    float acc[4][4] = {};

    for (int k0 = 0; k0 < IN_CH; k0 += BK) {
        float4 a4 = make_float4(0.f, 0.f, 0.f, 0.f);
        int arow = bm + ar;
        if (arow < N_NODES)
            a4 = *(const float4*)(g_agg + arow * IN_CH + k0 + ac);
        As[ac + 0][ar] = a4.x;
        As[ac + 1][ar] = a4.y;
        As[ac + 2][ar] = a4.z;
        As[ac + 3][ar] = a4.w;

        float4 b4 = *(const float4*)(W + (k0 + br) * OUT_CH + bn + bc);
        *(float4*)(&Bs[br][bc]) = b4;

        __syncthreads();

#pragma unroll
        for (int k = 0; k < BK; k++) {
            float4 av = *(const float4*)(&As[k][ty * 4]);
            float4 bv = *(const float4*)(&Bs[k][tx * 4]);
            acc[0][0] += av.x * bv.x; acc[0][1] += av.x * bv.y;
            acc[0][2] += av.x * bv.z; acc[0][3] += av.x * bv.w;
            acc[1][0] += av.y * bv.x; acc[1][1] += av.y * bv.y;
            acc[1][2] += av.y * bv.z; acc[1][3] += av.y * bv.w;
            acc[2][0] += av.z * bv.x; acc[2][1] += av.z * bv.y;
            acc[2][2] += av.z * bv.z; acc[2][3] += av.z * bv.w;
            acc[3][0] += av.w * bv.x; acc[3][1] += av.w * bv.y;
            acc[3][2] += av.w * bv.z; acc[3][3] += av.w * bv.w;
        }
        __syncthreads();
    }

    float4 bb = *(const float4*)(bias + bn + tx * 4);
#pragma unroll
    for (int i = 0; i < 4; i++) {
        int row = bm + ty * 4 + i;
        if (row < N_NODES) {
            float4 o;
            o.x = acc[i][0] + bb.x;
            o.y = acc[i][1] + bb.y;
            o.z = acc[i][2] + bb.z;
            o.w = acc[i][3] + bb.w;
            *(float4*)(out + row * OUT_CH + bn + tx * 4) = o;
        }
    }
}

// ---------------------------------------------------------------------------
extern "C" void kernel_launch(void* const* d_in, const int* in_sizes, int n_in,
                              void* d_out, int out_size) {
    const float* x  = (const float*)d_in[0];
    const float* W  = (const float*)d_in[1];
    const float* b  = (const float*)d_in[2];
    const int*   ei = (const int*)d_in[3];     // int32 (JAX x64 disabled)
    const float* ew = (const float*)d_in[4];
    float* out = (float*)d_out;

    k_init_deg<<<(N_NODES + 255) / 256, 256>>>();
    k_edge_deg<<<(N_EDGES + 255) / 256, 256>>>(ei, ew);
    k_dinv<<<(N_NODES + 255) / 256, 256>>>();
    k_selfloop<<<(N_NODES * 32 + 255) / 256, 256>>>(x);
    k_scatter<<<(N_EDGES * 32 + 255) / 256, 256>>>(ei, x);

    dim3 g(OUT_CH / BN, (N_NODES + BM - 1) / BM);
    k_gemm<<<g, 256>>>(W, b, out);
}

// round 6
// speedup vs baseline: 1.4065x; 1.4065x over previous
#include <cuda_runtime.h>
#include <cuda_bf16.h>
#include <math.h>

#define N_NODES 50000
#define N_EDGES 500000
#define IN_CH   128
#define OUT_CH  256

// Scratch (device globals — no allocation allowed)
__device__ __align__(16) float g_agg[N_NODES * IN_CH];   // Â·x  (25.6 MB)
__device__ float g_deg[N_NODES];
__device__ float g_dinv[N_NODES];
__device__ float g_ew[N_EDGES];

// ---------------------------------------------------------------------------
// 1. init degree with self-loop weight 1
__global__ void k_init_deg() {
    int i = blockIdx.x * blockDim.x + threadIdx.x;
    if (i < N_NODES) g_deg[i] = 1.0f;
}

// 2. sigmoid(edge_weight), accumulate degree on target node (int32 indices)
__global__ void k_edge_deg(const int* __restrict__ ei,
                           const float* __restrict__ w) {
    int e = blockIdx.x * blockDim.x + threadIdx.x;
    if (e < N_EDGES) {
        float s = 1.0f / (1.0f + expf(-w[e]));
        g_ew[e] = s;
        int col = ei[N_EDGES + e];
        if ((unsigned)col < N_NODES)
            atomicAdd(&g_deg[col], s);
    }
}

// 3. dinv = rsqrt(deg)
__global__ void k_dinv() {
    int i = blockIdx.x * blockDim.x + threadIdx.x;
    if (i < N_NODES) g_dinv[i] = rsqrtf(g_deg[i]);
}

// 4. self-loop contribution: agg[i] = x[i] * dinv[i]^2
__global__ void k_selfloop(const float* __restrict__ x) {
    int t = blockIdx.x * blockDim.x + threadIdx.x;
    int i = t >> 5;
    int c = (t & 31) << 2;
    if (i < N_NODES) {
        float di = g_dinv[i];
        float s = di * di;
        float4 v = *(const float4*)(x + i * IN_CH + c);
        v.x *= s; v.y *= s; v.z *= s; v.w *= s;
        *(float4*)(g_agg + i * IN_CH + c) = v;
    }
}

// 5. edge scatter: agg[col] += x[row] * norm.  32 threads/edge, one
//    red.global.add.v4.f32 per lane (4 channels) — 16M vector reds.
__global__ void k_scatter(const int* __restrict__ ei,
                          const float* __restrict__ x) {
    int t = blockIdx.x * blockDim.x + threadIdx.x;
    int e = t >> 5;
    if (e >= N_EDGES) return;
    int c = (t & 31) << 2;
    int row = ei[e];
    int col = ei[N_EDGES + e];
    if ((unsigned)row >= N_NODES || (unsigned)col >= N_NODES) return;
    float norm = g_dinv[row] * g_ew[e] * g_dinv[col];
    float4 v = *(const float4*)(x + row * IN_CH + c);
    float vx = v.x * norm, vy = v.y * norm, vz = v.z * norm, vw = v.w * norm;
    float* dst = g_agg + col * IN_CH + c;
    asm volatile("red.global.add.v4.f32 [%0], {%1, %2, %3, %4};"
                 :: "l"(dst), "f"(vx), "f"(vy), "f"(vz), "f"(vw)
                 : "memory");
}

// ---------------------------------------------------------------------------
// 6. GEMM via tf32 mma.sync.m16n8k8:
//    out[50000,256] = agg[50000,128] @ W[128,256] + b
//    Block: 256 thr (8 warps, 4x2), tile 128x64, BK=32. Warp tile 32x32.
#define GBM 128
#define GBN 64
#define GBK 32
#define AS_STRIDE 36   // bank = 4*(m%8)+k%4 == lane -> conflict-free frag loads
#define BS_STRIDE 72   // bank = 8*(k%4)+n%8 == lane -> conflict-free

__device__ __forceinline__ unsigned f2tf32(float f) {
    unsigned u;
    asm("cvt.rna.tf32.f32 %0, %1;" : "=r"(u) : "f"(f));
    return u;
}

__global__ __launch_bounds__(256) void k_gemm_tf32(const float* __restrict__ W,
                                                   const float* __restrict__ bias,
                                                   float* __restrict__ out) {
    __shared__ unsigned As[GBM][AS_STRIDE];   // 18 KB
    __shared__ unsigned Bs[GBK][BS_STRIDE];   // 9 KB

    int tid  = threadIdx.x;
    int warp = tid >> 5;
    int lane = tid & 31;
    int grp  = lane >> 2;     // 0..7
    int kq   = lane & 3;      // 0..3
    int bm = blockIdx.y * GBM;
    int bn = blockIdx.x * GBN;
    int wm = (warp & 3) * 32;   // warp m offset within tile
    int wn = (warp >> 2) * 32;  // warp n offset within tile

    float c[2][4][4];
#pragma unroll
    for (int mt = 0; mt < 2; mt++)
#pragma unroll
        for (int nt = 0; nt < 4; nt++)
#pragma unroll
            for (int r = 0; r < 4; r++) c[mt][nt][r] = 0.f;

    for (int k0 = 0; k0 < IN_CH; k0 += GBK) {
        // Load A tile (128x32): 1024 float4 by 256 threads, 4 each
#pragma unroll
        for (int r = 0; r < 4; r++) {
            int i = tid + 256 * r;
            int row = i >> 3;
            int c4  = (i & 7) << 2;
            float4 v = make_float4(0.f, 0.f, 0.f, 0.f);
            if (bm + row < N_NODES)
                v = *(const float4*)(g_agg + (size_t)(bm + row) * IN_CH + k0 + c4);
            As[row][c4 + 0] = f2tf32(v.x);
            As[row][c4 + 1] = f2tf32(v.y);
            As[row][c4 + 2] = f2tf32(v.z);
            As[row][c4 + 3] = f2tf32(v.w);
        }
        // Load B tile (32x64): 512 float4 by 256 threads, 2 each
#pragma unroll
        for (int r = 0; r < 2; r++) {
            int i = tid + 256 * r;
            int row = i >> 4;
            int c4  = (i & 15) << 2;
            float4 v = *(const float4*)(W + (size_t)(k0 + row) * OUT_CH + bn + c4);
            Bs[row][c4 + 0] = f2tf32(v.x);
            Bs[row][c4 + 1] = f2tf32(v.y);
            Bs[row][c4 + 2] = f2tf32(v.z);
            Bs[row][c4 + 3] = f2tf32(v.w);
        }
        __syncthreads();

#pragma unroll
        for (int kk = 0; kk < GBK; kk += 8) {
            unsigned a[2][4], bf[4][2];
#pragma unroll
            for (int mt = 0; mt < 2; mt++) {
                int r0 = wm + mt * 16 + grp;
                a[mt][0] = As[r0][kk + kq];
                a[mt][1] = As[r0 + 8][kk + kq];
                a[mt][2] = As[r0][kk + kq + 4];
                a[mt][3] = As[r0 + 8][kk + kq + 4];
            }
#pragma unroll
            for (int nt = 0; nt < 4; nt++) {
                int n0 = wn + nt * 8 + grp;
                bf[nt][0] = Bs[kk + kq][n0];
                bf[nt][1] = Bs[kk + kq + 4][n0];
            }
#pragma unroll
            for (int mt = 0; mt < 2; mt++)
#pragma unroll
                for (int nt = 0; nt < 4; nt++) {
                    asm volatile(
                        "mma.sync.aligned.m16n8k8.row.col.f32.tf32.tf32.f32 "
                        "{%0,%1,%2,%3}, {%4,%5,%6,%7}, {%8,%9}, {%0,%1,%2,%3};"
                        : "+f"(c[mt][nt][0]), "+f"(c[mt][nt][1]),
                          "+f"(c[mt][nt][2]), "+f"(c[mt][nt][3])
                        : "r"(a[mt][0]), "r"(a[mt][1]), "r"(a[mt][2]), "r"(a[mt][3]),
                          "r"(bf[nt][0]), "r"(bf[nt][1]));
                }
        }
        __syncthreads();
    }

    // Epilogue: add bias, store (float2 per half-fragment)
#pragma unroll
    for (int mt = 0; mt < 2; mt++) {
#pragma unroll
        for (int nt = 0; nt < 4; nt++) {
            int row0 = bm + wm + mt * 16 + grp;
            int col0 = bn + wn + nt * 8 + kq * 2;
            float2 bb = *(const float2*)(bias + col0);
            if (row0 < N_NODES) {
                float2 o = make_float2(c[mt][nt][0] + bb.x, c[mt][nt][1] + bb.y);
                *(float2*)(out + (size_t)row0 * OUT_CH + col0) = o;
            }
            if (row0 + 8 < N_NODES) {
                float2 o = make_float2(c[mt][nt][2] + bb.x, c[mt][nt][3] + bb.y);
                *(float2*)(out + (size_t)(row0 + 8) * OUT_CH + col0) = o;
            }
        }
    }
}

// ---------------------------------------------------------------------------
extern "C" void kernel_launch(void* const* d_in, const int* in_sizes, int n_in,
                              void* d_out, int out_size) {
    const float* x  = (const float*)d_in[0];
    const float* W  = (const float*)d_in[1];
    const float* b  = (const float*)d_in[2];
    const int*   ei = (const int*)d_in[3];     // int32 (JAX x64 disabled)
    const float* ew = (const float*)d_in[4];
    float* out = (float*)d_out;

    k_init_deg<<<(N_NODES + 255) / 256, 256>>>();
    k_edge_deg<<<(N_EDGES + 255) / 256, 256>>>(ei, ew);
    k_dinv<<<(N_NODES + 255) / 256, 256>>>();
    k_selfloop<<<(N_NODES * 32 + 255) / 256, 256>>>(x);
    k_scatter<<<(N_EDGES * 32 + 255) / 256, 256>>>(ei, x);

    dim3 g(OUT_CH / GBN, (N_NODES + GBM - 1) / GBM);
    k_gemm_tf32<<<g, 256>>>(W, b, out);
}

// round 10
// speedup vs baseline: 1.4592x; 1.0374x over previous
#include <cuda_runtime.h>
#include <cuda_bf16.h>
#include <math.h>

#define N_NODES 50000
#define N_EDGES 500000
#define IN_CH   128
#define OUT_CH  256

// Scratch (device globals — no allocation allowed)
__device__ __align__(16) float g_agg[N_NODES * IN_CH];   // Â·x  (25.6 MB)
__device__ float g_deg[N_NODES];
__device__ float g_dinv[N_NODES];
__device__ int   g_cnt[N_NODES];
__device__ int   g_rowptr[N_NODES + 1];
__device__ int   g_cursor[N_NODES];
__device__ __align__(8) int2 g_csr[N_EDGES];   // (src row, norm bits)

__device__ __forceinline__ float sigmoidf_(float v) {
    return 1.0f / (1.0f + expf(-v));
}

// ---------------------------------------------------------------------------
// 1. init: deg = 1 (self-loop), cnt = 0
__global__ void k_init() {
    int i = blockIdx.x * blockDim.x + threadIdx.x;
    if (i < N_NODES) { g_deg[i] = 1.0f; g_cnt[i] = 0; }
}

// 2. sigmoid(edge_weight) -> deg accumulation + target count
__global__ void k_edge_deg(const int* __restrict__ ei,
                           const float* __restrict__ w) {
    int e = blockIdx.x * blockDim.x + threadIdx.x;
    if (e < N_EDGES) {
        int col = ei[N_EDGES + e];
        int row = ei[e];
        if ((unsigned)col < N_NODES && (unsigned)row < N_NODES) {
            atomicAdd(&g_deg[col], sigmoidf_(w[e]));
            atomicAdd(&g_cnt[col], 1);
        }
    }
}

// 3. dinv = rsqrt(deg)
__global__ void k_dinv() {
    int i = blockIdx.x * blockDim.x + threadIdx.x;
    if (i < N_NODES) g_dinv[i] = rsqrtf(g_deg[i]);
}

// 4. exclusive prefix scan of g_cnt -> g_rowptr, g_cursor.  One block.
#define SCAN_T 1024
__global__ __launch_bounds__(SCAN_T) void k_scan() {
    __shared__ int part[SCAN_T];
    const int CH = (N_NODES + SCAN_T - 1) / SCAN_T;   // 49
    int t = threadIdx.x;
    int base = t * CH;
    int s = 0;
#pragma unroll 4
    for (int j = 0; j < CH; j++) {
        int idx = base + j;
        if (idx < N_NODES) s += g_cnt[idx];
    }
    part[t] = s;
    __syncthreads();
    // Hillis-Steele inclusive scan
    for (int off = 1; off < SCAN_T; off <<= 1) {
        int v = (t >= off) ? part[t - off] : 0;
        __syncthreads();
        part[t] += v;
        __syncthreads();
    }
    int run = part[t] - s;   // exclusive start of this chunk
    for (int j = 0; j < CH; j++) {
        int idx = base + j;
        if (idx < N_NODES) {
            g_rowptr[idx] = run;
            g_cursor[idx] = run;
            run += g_cnt[idx];
        }
    }
    if (t == SCAN_T - 1) g_rowptr[N_NODES] = part[SCAN_T - 1];
}

// 5. fill CSR: (src row, norm) per edge, grouped by target col
__global__ void k_fill(const int* __restrict__ ei,
                       const float* __restrict__ w) {
    int e = blockIdx.x * blockDim.x + threadIdx.x;
    if (e >= N_EDGES) return;
    int row = ei[e];
    int col = ei[N_EDGES + e];
    if ((unsigned)row >= N_NODES || (unsigned)col >= N_NODES) return;
    float norm = g_dinv[row] * sigmoidf_(w[e]) * g_dinv[col];
    int pos = atomicAdd(&g_cursor[col], 1);
    g_csr[pos] = make_int2(row, __float_as_int(norm));
}

// 6. gather-aggregate (warp per node, self-loop fused):
//    agg[i] = x[i]*dinv[i]^2 + sum_{(row,nm) in csr[i]} x[row]*nm
__global__ void k_aggregate(const float* __restrict__ x) {
    int t = blockIdx.x * blockDim.x + threadIdx.x;
    int i = t >> 5;
    if (i >= N_NODES) return;
    int c = (t & 31) << 2;

    float di = g_dinv[i];
    float sl = di * di;
    float4 acc = *(const float4*)(x + (size_t)i * IN_CH + c);
    acc.x *= sl; acc.y *= sl; acc.z *= sl; acc.w *= sl;

    int p   = g_rowptr[i];
    int end = g_rowptr[i + 1];
    for (; p < end; p++) {
        int2 pr = g_csr[p];                 // broadcast across warp
        float nm = __int_as_float(pr.y);
        float4 v = *(const float4*)(x + (size_t)pr.x * IN_CH + c);
        acc.x += v.x * nm; acc.y += v.y * nm;
        acc.z += v.z * nm; acc.w += v.w * nm;
    }
    *(float4*)(g_agg + (size_t)i * IN_CH + c) = acc;
}

// ---------------------------------------------------------------------------
// 7. GEMM via tf32 mma.sync.m16n8k8:
//    out[50000,256] = agg[50000,128] @ W[128,256] + b
#define GBM 128
#define GBN 64
#define GBK 32
#define AS_STRIDE 36
#define BS_STRIDE 72

__device__ __forceinline__ unsigned f2tf32(float f) {
    unsigned u;
    asm("cvt.rna.tf32.f32 %0, %1;" : "=r"(u) : "f"(f));
    return u;
}

__global__ __launch_bounds__(256) void k_gemm_tf32(const float* __restrict__ W,
                                                   const float* __restrict__ bias,
                                                   float* __restrict__ out) {
    __shared__ unsigned As[GBM][AS_STRIDE];
    __shared__ unsigned Bs[GBK][BS_STRIDE];

    int tid  = threadIdx.x;
    int warp = tid >> 5;
    int lane = tid & 31;
    int grp  = lane >> 2;
    int kq   = lane & 3;
    int bm = blockIdx.y * GBM;
    int bn = blockIdx.x * GBN;
    int wm = (warp & 3) * 32;
    int wn = (warp >> 2) * 32;

    float c[2][4][4];
#pragma unroll
    for (int mt = 0; mt < 2; mt++)
#pragma unroll
        for (int nt = 0; nt < 4; nt++)
#pragma unroll
            for (int r = 0; r < 4; r++) c[mt][nt][r] = 0.f;

    for (int k0 = 0; k0 < IN_CH; k0 += GBK) {
#pragma unroll
        for (int r = 0; r < 4; r++) {
            int i = tid + 256 * r;
            int row = i >> 3;
            int c4  = (i & 7) << 2;
            float4 v = make_float4(0.f, 0.f, 0.f, 0.f);
            if (bm + row < N_NODES)
                v = *(const float4*)(g_agg + (size_t)(bm + row) * IN_CH + k0 + c4);
            As[row][c4 + 0] = f2tf32(v.x);
            As[row][c4 + 1] = f2tf32(v.y);
            As[row][c4 + 2] = f2tf32(v.z);
            As[row][c4 + 3] = f2tf32(v.w);
        }
#pragma unroll
        for (int r = 0; r < 2; r++) {
            int i = tid + 256 * r;
            int row = i >> 4;
            int c4  = (i & 15) << 2;
            float4 v = *(const float4*)(W + (size_t)(k0 + row) * OUT_CH + bn + c4);
            Bs[row][c4 + 0] = f2tf32(v.x);
            Bs[row][c4 + 1] = f2tf32(v.y);
            Bs[row][c4 + 2] = f2tf32(v.z);
            Bs[row][c4 + 3] = f2tf32(v.w);
        }
        __syncthreads();

#pragma unroll
        for (int kk = 0; kk < GBK; kk += 8) {
            unsigned a[2][4], bf[4][2];
#pragma unroll
            for (int mt = 0; mt < 2; mt++) {
                int r0 = wm + mt * 16 + grp;
                a[mt][0] = As[r0][kk + kq];
                a[mt][1] = As[r0 + 8][kk + kq];
                a[mt][2] = As[r0][kk + kq + 4];
                a[mt][3] = As[r0 + 8][kk + kq + 4];
            }
#pragma unroll
            for (int nt = 0; nt < 4; nt++) {
                int n0 = wn + nt * 8 + grp;
                bf[nt][0] = Bs[kk + kq][n0];
                bf[nt][1] = Bs[kk + kq + 4][n0];
            }
#pragma unroll
            for (int mt = 0; mt < 2; mt++)
#pragma unroll
                for (int nt = 0; nt < 4; nt++) {
                    asm volatile(
                        "mma.sync.aligned.m16n8k8.row.col.f32.tf32.tf32.f32 "
                        "{%0,%1,%2,%3}, {%4,%5,%6,%7}, {%8,%9}, {%0,%1,%2,%3};"
                        : "+f"(c[mt][nt][0]), "+f"(c[mt][nt][1]),
                          "+f"(c[mt][nt][2]), "+f"(c[mt][nt][3])
                        : "r"(a[mt][0]), "r"(a[mt][1]), "r"(a[mt][2]), "r"(a[mt][3]),
                          "r"(bf[nt][0]), "r"(bf[nt][1]));
                }
        }
        __syncthreads();
    }

#pragma unroll
    for (int mt = 0; mt < 2; mt++) {
#pragma unroll
        for (int nt = 0; nt < 4; nt++) {
            int row0 = bm + wm + mt * 16 + grp;
            int col0 = bn + wn + nt * 8 + kq * 2;
            float2 bb = *(const float2*)(bias + col0);
            if (row0 < N_NODES) {
                float2 o = make_float2(c[mt][nt][0] + bb.x, c[mt][nt][1] + bb.y);
                *(float2*)(out + (size_t)row0 * OUT_CH + col0) = o;
            }
            if (row0 + 8 < N_NODES) {
                float2 o = make_float2(c[mt][nt][2] + bb.x, c[mt][nt][3] + bb.y);
                *(float2*)(out + (size_t)(row0 + 8) * OUT_CH + col0) = o;
            }
        }
    }
}

// ---------------------------------------------------------------------------
extern "C" void kernel_launch(void* const* d_in, const int* in_sizes, int n_in,
                              void* d_out, int out_size) {
    const float* x  = (const float*)d_in[0];
    const float* W  = (const float*)d_in[1];
    const float* b  = (const float*)d_in[2];
    const int*   ei = (const int*)d_in[3];     // int32 (JAX x64 disabled)
    const float* ew = (const float*)d_in[4];
    float* out = (float*)d_out;

    k_init<<<(N_NODES + 255) / 256, 256>>>();
    k_edge_deg<<<(N_EDGES + 255) / 256, 256>>>(ei, ew);
    k_dinv<<<(N_NODES + 255) / 256, 256>>>();
    k_scan<<<1, SCAN_T>>>();
    k_fill<<<(N_EDGES + 255) / 256, 256>>>(ei, ew);
    k_aggregate<<<(N_NODES * 32 + 255) / 256, 256>>>(x);

    dim3 g(OUT_CH / GBN, (N_NODES + GBM - 1) / GBM);
    k_gemm_tf32<<<g, 256>>>(W, b, out);
}

// round 12
// speedup vs baseline: 2.5333x; 1.7361x over previous
#include <cuda_runtime.h>
#include <cuda_bf16.h>
#include <math.h>

#define N_NODES 50000
#define N_EDGES 500000
#define IN_CH   128
#define OUT_CH  256

// Scratch (device globals — no allocation allowed)
__device__ __align__(16) float g_agg[N_NODES * IN_CH];   // Â·x  (25.6 MB)
__device__ float g_deg[N_NODES];
__device__ float g_dinv[N_NODES];
__device__ int   g_cnt[N_NODES];
__device__ int   g_rowptr[N_NODES + 1];
__device__ int   g_cursor[N_NODES];
__device__ __align__(8) int2 g_csr[N_EDGES];   // (src row, norm bits)

#define SB  256
#define NSB ((N_NODES + SB - 1) / SB)   // 196
__device__ int g_bsum[NSB];
__device__ int g_boff[NSB];

__device__ __forceinline__ float sigmoidf_(float v) {
    return 1.0f / (1.0f + expf(-v));
}

// ---------------------------------------------------------------------------
// 1. init: deg = 1 (self-loop), cnt = 0
__global__ void k_init() {
    int i = blockIdx.x * blockDim.x + threadIdx.x;
    if (i < N_NODES) { g_deg[i] = 1.0f; g_cnt[i] = 0; }
}

// 2. sigmoid(edge_weight) -> deg accumulation + target count
__global__ void k_edge_deg(const int* __restrict__ ei,
                           const float* __restrict__ w) {
    int e = blockIdx.x * blockDim.x + threadIdx.x;
    if (e < N_EDGES) {
        int col = ei[N_EDGES + e];
        int row = ei[e];
        if ((unsigned)col < N_NODES && (unsigned)row < N_NODES) {
            atomicAdd(&g_deg[col], sigmoidf_(w[e]));
            atomicAdd(&g_cnt[col], 1);
        }
    }
}

// 3. dinv = rsqrt(deg)
__global__ void k_dinv() {
    int i = blockIdx.x * blockDim.x + threadIdx.x;
    if (i < N_NODES) g_dinv[i] = rsqrtf(g_deg[i]);
}

// ---------------------------------------------------------------------------
// 4. device-wide exclusive scan of g_cnt (3 phases, all parallel)
// Phase A: per-block reduction of 256 counts
__global__ __launch_bounds__(SB) void k_scan_a() {
    __shared__ int warpsum[8];
    int t = threadIdx.x;
    int idx = blockIdx.x * SB + t;
    int v = (idx < N_NODES) ? g_cnt[idx] : 0;
    int s = v;
#pragma unroll
    for (int o = 16; o > 0; o >>= 1) s += __shfl_down_sync(~0u, s, o);
    if ((t & 31) == 0) warpsum[t >> 5] = s;
    __syncthreads();
    if (t < 8) {
        int ws = warpsum[t];
#pragma unroll
        for (int o = 4; o > 0; o >>= 1) ws += __shfl_down_sync(0xffu, ws, o);
        if (t == 0) g_bsum[blockIdx.x] = ws;
    }
}

// Phase B: single block scans NSB block sums -> exclusive offsets + total
__global__ __launch_bounds__(SB) void k_scan_b() {
    __shared__ int sh[SB];
    int t = threadIdx.x;
    int v = (t < NSB) ? g_bsum[t] : 0;
    sh[t] = v;
    __syncthreads();
    for (int off = 1; off < SB; off <<= 1) {
        int u = (t >= off) ? sh[t - off] : 0;
        __syncthreads();
        sh[t] += u;
        __syncthreads();
    }
    if (t < NSB) g_boff[t] = sh[t] - v;      // exclusive
    if (t == SB - 1) g_rowptr[N_NODES] = sh[t];
}

// Phase C: per-block local exclusive scan + block offset -> rowptr, cursor
__global__ __launch_bounds__(SB) void k_scan_c() {
    __shared__ int sh[SB];
    int t = threadIdx.x;
    int idx = blockIdx.x * SB + t;
    int v = (idx < N_NODES) ? g_cnt[idx] : 0;
    sh[t] = v;
    __syncthreads();
    for (int off = 1; off < SB; off <<= 1) {
        int u = (t >= off) ? sh[t - off] : 0;
        __syncthreads();
        sh[t] += u;
        __syncthreads();
    }
    if (idx < N_NODES) {
        int excl = sh[t] - v + g_boff[blockIdx.x];
        g_rowptr[idx] = excl;
        g_cursor[idx] = excl;
    }
}

// ---------------------------------------------------------------------------
// 5. fill CSR: (src row, norm) per edge, grouped by target col
__global__ void k_fill(const int* __restrict__ ei,
                       const float* __restrict__ w) {
    int e = blockIdx.x * blockDim.x + threadIdx.x;
    if (e >= N_EDGES) return;
    int row = ei[e];
    int col = ei[N_EDGES + e];
    if ((unsigned)row >= N_NODES || (unsigned)col >= N_NODES) return;
    float norm = g_dinv[row] * sigmoidf_(w[e]) * g_dinv[col];
    int pos = atomicAdd(&g_cursor[col], 1);
    g_csr[pos] = make_int2(row, __float_as_int(norm));
}

// 6. gather-aggregate (warp per node, self-loop fused)
__global__ void k_aggregate(const float* __restrict__ x) {
    int t = blockIdx.x * blockDim.x + threadIdx.x;
    int i = t >> 5;
    if (i >= N_NODES) return;
    int c = (t & 31) << 2;

    float di = g_dinv[i];
    float sl = di * di;
    float4 acc = *(const float4*)(x + (size_t)i * IN_CH + c);
    acc.x *= sl; acc.y *= sl; acc.z *= sl; acc.w *= sl;

    int p   = g_rowptr[i];
    int end = g_rowptr[i + 1];
    for (; p < end; p++) {
        int2 pr = g_csr[p];                 // broadcast across warp
        float nm = __int_as_float(pr.y);
        float4 v = *(const float4*)(x + (size_t)pr.x * IN_CH + c);
        acc.x += v.x * nm; acc.y += v.y * nm;
        acc.z += v.z * nm; acc.w += v.w * nm;
    }
    *(float4*)(g_agg + (size_t)i * IN_CH + c) = acc;
}

// ---------------------------------------------------------------------------
// 7. GEMM via tf32 mma.sync.m16n8k8:
//    out[50000,256] = agg[50000,128] @ W[128,256] + b
#define GBM 128
#define GBN 64
#define GBK 32
#define AS_STRIDE 36
#define BS_STRIDE 72

__device__ __forceinline__ unsigned f2tf32(float f) {
    unsigned u;
    asm("cvt.rna.tf32.f32 %0, %1;" : "=r"(u) : "f"(f));
    return u;
}

__global__ __launch_bounds__(256) void k_gemm_tf32(const float* __restrict__ W,
                                                   const float* __restrict__ bias,
                                                   float* __restrict__ out) {
    __shared__ unsigned As[GBM][AS_STRIDE];
    __shared__ unsigned Bs[GBK][BS_STRIDE];

    int tid  = threadIdx.x;
    int warp = tid >> 5;
    int lane = tid & 31;
    int grp  = lane >> 2;
    int kq   = lane & 3;
    int bm = blockIdx.y * GBM;
    int bn = blockIdx.x * GBN;
    int wm = (warp & 3) * 32;
    int wn = (warp >> 2) * 32;

    float c[2][4][4];
#pragma unroll
    for (int mt = 0; mt < 2; mt++)
#pragma unroll
        for (int nt = 0; nt < 4; nt++)
#pragma unroll
            for (int r = 0; r < 4; r++) c[mt][nt][r] = 0.f;

    for (int k0 = 0; k0 < IN_CH; k0 += GBK) {
#pragma unroll
        for (int r = 0; r < 4; r++) {
            int i = tid + 256 * r;
            int row = i >> 3;
            int c4  = (i & 7) << 2;
            float4 v = make_float4(0.f, 0.f, 0.f, 0.f);
            if (bm + row < N_NODES)
                v = *(const float4*)(g_agg + (size_t)(bm + row) * IN_CH + k0 + c4);
            As[row][c4 + 0] = f2tf32(v.x);
            As[row][c4 + 1] = f2tf32(v.y);
            As[row][c4 + 2] = f2tf32(v.z);
            As[row][c4 + 3] = f2tf32(v.w);
        }
#pragma unroll
        for (int r = 0; r < 2; r++) {
            int i = tid + 256 * r;
            int row = i >> 4;
            int c4  = (i & 15) << 2;
            float4 v = *(const float4*)(W + (size_t)(k0 + row) * OUT_CH + bn + c4);
            Bs[row][c4 + 0] = f2tf32(v.x);
            Bs[row][c4 + 1] = f2tf32(v.y);
            Bs[row][c4 + 2] = f2tf32(v.z);
            Bs[row][c4 + 3] = f2tf32(v.w);
        }
        __syncthreads();

#pragma unroll
        for (int kk = 0; kk < GBK; kk += 8) {
            unsigned a[2][4], bf[4][2];
#pragma unroll
            for (int mt = 0; mt < 2; mt++) {
                int r0 = wm + mt * 16 + grp;
                a[mt][0] = As[r0][kk + kq];
                a[mt][1] = As[r0 + 8][kk + kq];
                a[mt][2] = As[r0][kk + kq + 4];
                a[mt][3] = As[r0 + 8][kk + kq + 4];
            }
#pragma unroll
            for (int nt = 0; nt < 4; nt++) {
                int n0 = wn + nt * 8 + grp;
                bf[nt][0] = Bs[kk + kq][n0];
                bf[nt][1] = Bs[kk + kq + 4][n0];
            }
#pragma unroll
            for (int mt = 0; mt < 2; mt++)
#pragma unroll
                for (int nt = 0; nt < 4; nt++) {
                    asm volatile(
                        "mma.sync.aligned.m16n8k8.row.col.f32.tf32.tf32.f32 "
                        "{%0,%1,%2,%3}, {%4,%5,%6,%7}, {%8,%9}, {%0,%1,%2,%3};"
                        : "+f"(c[mt][nt][0]), "+f"(c[mt][nt][1]),
                          "+f"(c[mt][nt][2]), "+f"(c[mt][nt][3])
                        : "r"(a[mt][0]), "r"(a[mt][1]), "r"(a[mt][2]), "r"(a[mt][3]),
                          "r"(bf[nt][0]), "r"(bf[nt][1]));
                }
        }
        __syncthreads();
    }

#pragma unroll
    for (int mt = 0; mt < 2; mt++) {
#pragma unroll
        for (int nt = 0; nt < 4; nt++) {
            int row0 = bm + wm + mt * 16 + grp;
            int col0 = bn + wn + nt * 8 + kq * 2;
            float2 bb = *(const float2*)(bias + col0);
            if (row0 < N_NODES) {
                float2 o = make_float2(c[mt][nt][0] + bb.x, c[mt][nt][1] + bb.y);
                *(float2*)(out + (size_t)row0 * OUT_CH + col0) = o;
            }
            if (row0 + 8 < N_NODES) {
                float2 o = make_float2(c[mt][nt][2] + bb.x, c[mt][nt][3] + bb.y);
                *(float2*)(out + (size_t)(row0 + 8) * OUT_CH + col0) = o;
            }
        }
    }
}

// ---------------------------------------------------------------------------
extern "C" void kernel_launch(void* const* d_in, const int* in_sizes, int n_in,
                              void* d_out, int out_size) {
    const float* x  = (const float*)d_in[0];
    const float* W  = (const float*)d_in[1];
    const float* b  = (const float*)d_in[2];
    const int*   ei = (const int*)d_in[3];     // int32 (JAX x64 disabled)
    const float* ew = (const float*)d_in[4];
    float* out = (float*)d_out;

    k_init<<<(N_NODES + 255) / 256, 256>>>();
    k_edge_deg<<<(N_EDGES + 255) / 256, 256>>>(ei, ew);
    k_dinv<<<(N_NODES + 255) / 256, 256>>>();
    k_scan_a<<<NSB, SB>>>();
    k_scan_b<<<1, SB>>>();
    k_scan_c<<<NSB, SB>>>();
    k_fill<<<(N_EDGES + 255) / 256, 256>>>(ei, ew);
    k_aggregate<<<(N_NODES * 32 + 255) / 256, 256>>>(x);

    dim3 g(OUT_CH / GBN, (N_NODES + GBM - 1) / GBM);
    k_gemm_tf32<<<g, 256>>>(W, b, out);
}

// round 13
// speedup vs baseline: 2.5341x; 1.0003x over previous
#include <cuda_runtime.h>
#include <cuda_bf16.h>
#include <math.h>

#define N_NODES 50000
#define N_EDGES 500000
#define IN_CH   128
#define OUT_CH  256

// Scratch (device globals — no allocation allowed)
__device__ __align__(16) float g_agg[N_NODES * IN_CH];   // Â·x  (25.6 MB)
__device__ float g_deg[N_NODES];
__device__ float g_dinv[N_NODES];
__device__ float g_ew[N_EDGES];
__device__ int   g_cnt[N_NODES];
__device__ int   g_rowptr[N_NODES + 1];
__device__ int   g_cursor[N_NODES];
__device__ __align__(8) int2 g_csr[N_EDGES];   // (src row, norm bits)

#define SB  256
#define NSB ((N_NODES + SB - 1) / SB)   // 196
__device__ int g_bsum[NSB];
__device__ int g_boff[NSB];

__device__ __forceinline__ float sigmoidf_(float v) {
    return 1.0f / (1.0f + expf(-v));
}

// ---------------------------------------------------------------------------
// 1. init: deg = 1 (self-loop), cnt = 0
__global__ void k_init() {
    int i = blockIdx.x * blockDim.x + threadIdx.x;
    if (i < N_NODES) { g_deg[i] = 1.0f; g_cnt[i] = 0; }
}

// 2. sigmoid(edge_weight) -> g_ew, deg accumulation + target count
__global__ void k_edge_deg(const int* __restrict__ ei,
                           const float* __restrict__ w) {
    int e = blockIdx.x * blockDim.x + threadIdx.x;
    if (e < N_EDGES) {
        int col = ei[N_EDGES + e];
        int row = ei[e];
        float s = sigmoidf_(w[e]);
        g_ew[e] = s;
        if ((unsigned)col < N_NODES && (unsigned)row < N_NODES) {
            atomicAdd(&g_deg[col], s);
            atomicAdd(&g_cnt[col], 1);
        }
    }
}

// ---------------------------------------------------------------------------
// 3. device-wide exclusive scan of g_cnt (3 phases) + dinv fused into phase A
__global__ __launch_bounds__(SB) void k_scan_a() {
    __shared__ int warpsum[8];
    int t = threadIdx.x;
    int idx = blockIdx.x * SB + t;
    int v = 0;
    if (idx < N_NODES) {
        v = g_cnt[idx];
        g_dinv[idx] = rsqrtf(g_deg[idx]);   // fused dinv
    }
    int s = v;
#pragma unroll
    for (int o = 16; o > 0; o >>= 1) s += __shfl_down_sync(~0u, s, o);
    if ((t & 31) == 0) warpsum[t >> 5] = s;
    __syncthreads();
    if (t < 8) {
        int ws = warpsum[t];
#pragma unroll
        for (int o = 4; o > 0; o >>= 1) ws += __shfl_down_sync(0xffu, ws, o);
        if (t == 0) g_bsum[blockIdx.x] = ws;
    }
}

__global__ __launch_bounds__(SB) void k_scan_b() {
    __shared__ int sh[SB];
    int t = threadIdx.x;
    int v = (t < NSB) ? g_bsum[t] : 0;
    sh[t] = v;
    __syncthreads();
    for (int off = 1; off < SB; off <<= 1) {
        int u = (t >= off) ? sh[t - off] : 0;
        __syncthreads();
        sh[t] += u;
        __syncthreads();
    }
    if (t < NSB) g_boff[t] = sh[t] - v;
    if (t == SB - 1) g_rowptr[N_NODES] = sh[t];
}

__global__ __launch_bounds__(SB) void k_scan_c() {
    __shared__ int sh[SB];
    int t = threadIdx.x;
    int idx = blockIdx.x * SB + t;
    int v = (idx < N_NODES) ? g_cnt[idx] : 0;
    sh[t] = v;
    __syncthreads();
    for (int off = 1; off < SB; off <<= 1) {
        int u = (t >= off) ? sh[t - off] : 0;
        __syncthreads();
        sh[t] += u;
        __syncthreads();
    }
    if (idx < N_NODES) {
        int excl = sh[t] - v + g_boff[blockIdx.x];
        g_rowptr[idx] = excl;
        g_cursor[idx] = excl;
    }
}

// ---------------------------------------------------------------------------
// 4. fill CSR: (src row, norm) per edge, grouped by target col (reads g_ew)
__global__ void k_fill(const int* __restrict__ ei) {
    int e = blockIdx.x * blockDim.x + threadIdx.x;
    if (e >= N_EDGES) return;
    int row = ei[e];
    int col = ei[N_EDGES + e];
    if ((unsigned)row >= N_NODES || (unsigned)col >= N_NODES) return;
    float norm = g_dinv[row] * g_ew[e] * g_dinv[col];
    int pos = atomicAdd(&g_cursor[col], 1);
    g_csr[pos] = make_int2(row, __float_as_int(norm));
}

// 5. gather-aggregate (warp per node, self-loop fused, unroll x2 for MLP)
__global__ void k_aggregate(const float* __restrict__ x) {
    int t = blockIdx.x * blockDim.x + threadIdx.x;
    int i = t >> 5;
    if (i >= N_NODES) return;
    int c = (t & 31) << 2;

    float di = g_dinv[i];
    float sl = di * di;
    float4 acc = *(const float4*)(x + (size_t)i * IN_CH + c);
    acc.x *= sl; acc.y *= sl; acc.z *= sl; acc.w *= sl;

    int p   = g_rowptr[i];
    int end = g_rowptr[i + 1];
    for (; p + 1 < end; p += 2) {
        int2 a0 = g_csr[p];
        int2 a1 = g_csr[p + 1];
        float4 v0 = *(const float4*)(x + (size_t)a0.x * IN_CH + c);
        float4 v1 = *(const float4*)(x + (size_t)a1.x * IN_CH + c);
        float n0 = __int_as_float(a0.y);
        float n1 = __int_as_float(a1.y);
        acc.x += v0.x * n0; acc.y += v0.y * n0;
        acc.z += v0.z * n0; acc.w += v0.w * n0;
        acc.x += v1.x * n1; acc.y += v1.y * n1;
        acc.z += v1.z * n1; acc.w += v1.w * n1;
    }
    if (p < end) {
        int2 a0 = g_csr[p];
        float n0 = __int_as_float(a0.y);
        float4 v0 = *(const float4*)(x + (size_t)a0.x * IN_CH + c);
        acc.x += v0.x * n0; acc.y += v0.y * n0;
        acc.z += v0.z * n0; acc.w += v0.w * n0;
    }
    *(float4*)(g_agg + (size_t)i * IN_CH + c) = acc;
}

// ---------------------------------------------------------------------------
// 6. GEMM via tf32 mma.sync.m16n8k8, double-buffered smem, GBK=16:
//    out[50000,256] = agg[50000,128] @ W[128,256] + b
#define GBM 128
#define GBN 64
#define GBK 16
#define AS_STRIDE 20   // frag banks: 20*grp+kq mod 32 all distinct
#define BS_STRIDE 72
#define NKIT (IN_CH / GBK)   // 8

__device__ __forceinline__ unsigned f2tf32(float f) {
    unsigned u;
    asm("cvt.rna.tf32.f32 %0, %1;" : "=r"(u) : "f"(f));
    return u;
}

__global__ __launch_bounds__(256) void k_gemm_tf32(const float* __restrict__ W,
                                                   const float* __restrict__ bias,
                                                   float* __restrict__ out) {
    __shared__ unsigned As[2][GBM][AS_STRIDE];   // 20.5 KB
    __shared__ unsigned Bs[2][GBK][BS_STRIDE];   // 9.2 KB

    int tid  = threadIdx.x;
    int warp = tid >> 5;
    int lane = tid & 31;
    int grp  = lane >> 2;
    int kq   = lane & 3;
    int bm = blockIdx.y * GBM;
    int bn = blockIdx.x * GBN;
    int wm = (warp & 3) * 32;
    int wn = (warp >> 2) * 32;

    // Load mappings
    int a_row = tid >> 2;              // 0..63 per r-step (2 steps -> 128 rows)
    int a_c4  = (tid & 3) << 2;        // 0,4,8,12
    int b_row = tid >> 4;              // 0..15
    int b_c4  = (tid & 15) << 2;       // 0..60

    float c[2][4][4];
#pragma unroll
    for (int mt = 0; mt < 2; mt++)
#pragma unroll
        for (int nt = 0; nt < 4; nt++)
#pragma unroll
            for (int r = 0; r < 4; r++) c[mt][nt][r] = 0.f;

    // Prologue: load tile 0 into buffer 0
    float4 a4[2], b4;
#pragma unroll
    for (int r = 0; r < 2; r++) {
        int row = a_row + 64 * r;
        a4[r] = make_float4(0.f, 0.f, 0.f, 0.f);
        if (bm + row < N_NODES)
            a4[r] = *(const float4*)(g_agg + (size_t)(bm + row) * IN_CH + a_c4);
    }
    b4 = *(const float4*)(W + (size_t)b_row * OUT_CH + bn + b_c4);
#pragma unroll
    for (int r = 0; r < 2; r++) {
        int row = a_row + 64 * r;
        As[0][row][a_c4 + 0] = f2tf32(a4[r].x);
        As[0][row][a_c4 + 1] = f2tf32(a4[r].y);
        As[0][row][a_c4 + 2] = f2tf32(a4[r].z);
        As[0][row][a_c4 + 3] = f2tf32(a4[r].w);
    }
    Bs[0][b_row][b_c4 + 0] = f2tf32(b4.x);
    Bs[0][b_row][b_c4 + 1] = f2tf32(b4.y);
    Bs[0][b_row][b_c4 + 2] = f2tf32(b4.z);
    Bs[0][b_row][b_c4 + 3] = f2tf32(b4.w);
    __syncthreads();

    for (int it = 0; it < NKIT; it++) {
        int cur = it & 1;
        // Issue next tile's global loads before compute (latency overlap)
        if (it + 1 < NKIT) {
            int k0 = (it + 1) * GBK;
#pragma unroll
            for (int r = 0; r < 2; r++) {
                int row = a_row + 64 * r;
                a4[r] = make_float4(0.f, 0.f, 0.f, 0.f);
                if (bm + row < N_NODES)
                    a4[r] = *(const float4*)(g_agg + (size_t)(bm + row) * IN_CH + k0 + a_c4);
            }
            b4 = *(const float4*)(W + (size_t)(k0 + b_row) * OUT_CH + bn + b_c4);
        }

        // Compute on current buffer: kk = 0, 8
#pragma unroll
        for (int kk = 0; kk < GBK; kk += 8) {
            unsigned a[2][4], bf[4][2];
#pragma unroll
            for (int mt = 0; mt < 2; mt++) {
                int r0 = wm + mt * 16 + grp;
                a[mt][0] = As[cur][r0][kk + kq];
                a[mt][1] = As[cur][r0 + 8][kk + kq];
                a[mt][2] = As[cur][r0][kk + kq + 4];
                a[mt][3] = As[cur][r0 + 8][kk + kq + 4];
            }
#pragma unroll
            for (int nt = 0; nt < 4; nt++) {
                int n0 = wn + nt * 8 + grp;
                bf[nt][0] = Bs[cur][kk + kq][n0];
                bf[nt][1] = Bs[cur][kk + kq + 4][n0];
            }
#pragma unroll
            for (int mt = 0; mt < 2; mt++)
#pragma unroll
                for (int nt = 0; nt < 4; nt++) {
                    asm volatile(
                        "mma.sync.aligned.m16n8k8.row.col.f32.tf32.tf32.f32 "
                        "{%0,%1,%2,%3}, {%4,%5,%6,%7}, {%8,%9}, {%0,%1,%2,%3};"
                        : "+f"(c[mt][nt][0]), "+f"(c[mt][nt][1]),
                          "+f"(c[mt][nt][2]), "+f"(c[mt][nt][3])
                        : "r"(a[mt][0]), "r"(a[mt][1]), "r"(a[mt][2]), "r"(a[mt][3]),
                          "r"(bf[nt][0]), "r"(bf[nt][1]));
                }
        }

        // Store next tile into the other buffer
        if (it + 1 < NKIT) {
            int nxt = 1 - cur;
#pragma unroll
            for (int r = 0; r < 2; r++) {
                int row = a_row + 64 * r;
                As[nxt][row][a_c4 + 0] = f2tf32(a4[r].x);
                As[nxt][row][a_c4 + 1] = f2tf32(a4[r].y);
                As[nxt][row][a_c4 + 2] = f2tf32(a4[r].z);
                As[nxt][row][a_c4 + 3] = f2tf32(a4[r].w);
            }
            Bs[nxt][b_row][b_c4 + 0] = f2tf32(b4.x);
            Bs[nxt][b_row][b_c4 + 1] = f2tf32(b4.y);
            Bs[nxt][b_row][b_c4 + 2] = f2tf32(b4.z);
            Bs[nxt][b_row][b_c4 + 3] = f2tf32(b4.w);
        }
        __syncthreads();
    }

#pragma unroll
    for (int mt = 0; mt < 2; mt++) {
#pragma unroll
        for (int nt = 0; nt < 4; nt++) {
            int row0 = bm + wm + mt * 16 + grp;
            int col0 = bn + wn + nt * 8 + kq * 2;
            float2 bb = *(const float2*)(bias + col0);
            if (row0 < N_NODES) {
                float2 o = make_float2(c[mt][nt][0] + bb.x, c[mt][nt][1] + bb.y);
                *(float2*)(out + (size_t)row0 * OUT_CH + col0) = o;
            }
            if (row0 + 8 < N_NODES) {
                float2 o = make_float2(c[mt][nt][2] + bb.x, c[mt][nt][3] + bb.y);
                *(float2*)(out + (size_t)(row0 + 8) * OUT_CH + col0) = o;
            }
        }
    }
}

// ---------------------------------------------------------------------------
extern "C" void kernel_launch(void* const* d_in, const int* in_sizes, int n_in,
                              void* d_out, int out_size) {
    const float* x  = (const float*)d_in[0];
    const float* W  = (const float*)d_in[1];
    const float* b  = (const float*)d_in[2];
    const int*   ei = (const int*)d_in[3];     // int32 (JAX x64 disabled)
    const float* ew = (const float*)d_in[4];
    float* out = (float*)d_out;

    k_init<<<(N_NODES + 255) / 256, 256>>>();
    k_edge_deg<<<(N_EDGES + 255) / 256, 256>>>(ei, ew);
    k_scan_a<<<NSB, SB>>>();
    k_scan_b<<<1, SB>>>();
    k_scan_c<<<NSB, SB>>>();
    k_fill<<<(N_EDGES + 255) / 256, 256>>>(ei);
    k_aggregate<<<(N_NODES * 32 + 255) / 256, 256>>>(x);

    dim3 g(OUT_CH / GBN, (N_NODES + GBM - 1) / GBM);
    k_gemm_tf32<<<g, 256>>>(W, b, out);
}

// round 15
// speedup vs baseline: 2.6642x; 1.0513x over previous
#include <cuda_runtime.h>
#include <cuda_bf16.h>
#include <math.h>

#define N_NODES 50000
#define N_EDGES 500000
#define IN_CH   128
#define OUT_CH  256

// Scratch (device globals — no allocation allowed)
__device__ __align__(16) float g_agg[N_NODES * IN_CH];   // Â·x  (25.6 MB)
__device__ float g_deg[N_NODES];
__device__ float g_dinv[N_NODES];
__device__ float g_ew[N_EDGES];
__device__ int   g_cnt[N_NODES];
__device__ int   g_rowptr[N_NODES + 1];
__device__ int   g_cursor[N_NODES];
__device__ __align__(8) int2 g_csr[N_EDGES];   // (src row, norm bits)

#define SB  256
#define NSB ((N_NODES + SB - 1) / SB)   // 196
__device__ int g_bsum[NSB];

__device__ __forceinline__ float sigmoidf_(float v) {
    return 1.0f / (1.0f + expf(-v));
}

// ---------------------------------------------------------------------------
// 1. init: deg = 1 (self-loop), cnt = 0
__global__ void k_init() {
    int i = blockIdx.x * blockDim.x + threadIdx.x;
    if (i < N_NODES) { g_deg[i] = 1.0f; g_cnt[i] = 0; }
}

// 2. sigmoid(edge_weight) -> g_ew, deg accumulation + target count
__global__ void k_edge_deg(const int* __restrict__ ei,
                           const float* __restrict__ w) {
    int e = blockIdx.x * blockDim.x + threadIdx.x;
    if (e < N_EDGES) {
        int col = ei[N_EDGES + e];
        int row = ei[e];
        float s = sigmoidf_(w[e]);
        g_ew[e] = s;
        if ((unsigned)col < N_NODES && (unsigned)row < N_NODES) {
            atomicAdd(&g_deg[col], s);
            atomicAdd(&g_cnt[col], 1);
        }
    }
}

// ---------------------------------------------------------------------------
// 3a. per-block reduction of counts (+ fused dinv)
__global__ __launch_bounds__(SB) void k_scan_a() {
    __shared__ int warpsum[8];
    int t = threadIdx.x;
    int idx = blockIdx.x * SB + t;
    int v = 0;
    if (idx < N_NODES) {
        v = g_cnt[idx];
        g_dinv[idx] = rsqrtf(g_deg[idx]);   // fused dinv
    }
    int s = v;
#pragma unroll
    for (int o = 16; o > 0; o >>= 1) s += __shfl_down_sync(~0u, s, o);
    if ((t & 31) == 0) warpsum[t >> 5] = s;
    __syncthreads();
    if (t < 8) {
        int ws = warpsum[t];
#pragma unroll
        for (int o = 4; o > 0; o >>= 1) ws += __shfl_down_sync(0xffu, ws, o);
        if (t == 0) g_bsum[blockIdx.x] = ws;
    }
}

// 3b. merged: every block redundantly scans the 196 block sums (cheap),
//     derives its own exclusive offset, then does the local scan.
__global__ __launch_bounds__(SB) void k_scan_bc() {
    __shared__ int sh[SB];
    __shared__ int s_boff;
    int t = threadIdx.x;

    // scan of block sums
    int v = (t < NSB) ? g_bsum[t] : 0;
    sh[t] = v;
    __syncthreads();
    for (int off = 1; off < SB; off <<= 1) {
        int u = (t >= off) ? sh[t - off] : 0;
        __syncthreads();
        sh[t] += u;
        __syncthreads();
    }
    if (t == blockIdx.x) s_boff = sh[t] - v;          // exclusive offset
    if (blockIdx.x == 0 && t == SB - 1) g_rowptr[N_NODES] = sh[SB - 1];
    __syncthreads();
    int boff = s_boff;
    __syncthreads();

    // local scan of counts
    int idx = blockIdx.x * SB + t;
    int c = (idx < N_NODES) ? g_cnt[idx] : 0;
    sh[t] = c;
    __syncthreads();
    for (int off = 1; off < SB; off <<= 1) {
        int u = (t >= off) ? sh[t - off] : 0;
        __syncthreads();
        sh[t] += u;
        __syncthreads();
    }
    if (idx < N_NODES) {
        int excl = sh[t] - c + boff;
        g_rowptr[idx] = excl;
        g_cursor[idx] = excl;
    }
}

// ---------------------------------------------------------------------------
// 4. fill CSR: (src row, norm) per edge, grouped by target col (reads g_ew)
__global__ void k_fill(const int* __restrict__ ei) {
    int e = blockIdx.x * blockDim.x + threadIdx.x;
    if (e >= N_EDGES) return;
    int row = ei[e];
    int col = ei[N_EDGES + e];
    if ((unsigned)row >= N_NODES || (unsigned)col >= N_NODES) return;
    float norm = g_dinv[row] * g_ew[e] * g_dinv[col];
    int pos = atomicAdd(&g_cursor[col], 1);
    g_csr[pos] = make_int2(row, __float_as_int(norm));
}

// 5. gather-aggregate (warp per node, self-loop fused, unroll x2 for MLP)
__global__ void k_aggregate(const float* __restrict__ x) {
    int t = blockIdx.x * blockDim.x + threadIdx.x;
    int i = t >> 5;
    if (i >= N_NODES) return;
    int c = (t & 31) << 2;

    float di = g_dinv[i];
    float sl = di * di;
    float4 acc = *(const float4*)(x + (size_t)i * IN_CH + c);
    acc.x *= sl; acc.y *= sl; acc.z *= sl; acc.w *= sl;

    int p   = g_rowptr[i];
    int end = g_rowptr[i + 1];
    for (; p + 1 < end; p += 2) {
        int2 a0 = g_csr[p];
        int2 a1 = g_csr[p + 1];
        float4 v0 = *(const float4*)(x + (size_t)a0.x * IN_CH + c);
        float4 v1 = *(const float4*)(x + (size_t)a1.x * IN_CH + c);
        float n0 = __int_as_float(a0.y);
        float n1 = __int_as_float(a1.y);
        acc.x += v0.x * n0; acc.y += v0.y * n0;
        acc.z += v0.z * n0; acc.w += v0.w * n0;
        acc.x += v1.x * n1; acc.y += v1.y * n1;
        acc.z += v1.z * n1; acc.w += v1.w * n1;
    }
    if (p < end) {
        int2 a0 = g_csr[p];
        float n0 = __int_as_float(a0.y);
        float4 v0 = *(const float4*)(x + (size_t)a0.x * IN_CH + c);
        acc.x += v0.x * n0; acc.y += v0.y * n0;
        acc.z += v0.z * n0; acc.w += v0.w * n0;
    }
    *(float4*)(g_agg + (size_t)i * IN_CH + c) = acc;
}

// ---------------------------------------------------------------------------
// 6. GEMM via tf32 mma.sync.m16n8k8, double-buffered, 128x128 tile, GBK=16:
//    out[50000,256] = agg[50000,128] @ W[128,256] + b
#define GBM 128
#define GBN 128
#define GBK 16
#define AS_STRIDE 20    // frag banks: (20*grp+kq) mod 32 all distinct
#define BS_STRIDE 136   // 136 mod 32 = 8 -> (8*kq+grp) mod 32 all distinct
#define NKIT (IN_CH / GBK)   // 8

__device__ __forceinline__ unsigned f2tf32(float f) {
    unsigned u;
    asm("cvt.rna.tf32.f32 %0, %1;" : "=r"(u) : "f"(f));
    return u;
}

__global__ __launch_bounds__(256) void k_gemm_tf32(const float* __restrict__ W,
                                                   const float* __restrict__ bias,
                                                   float* __restrict__ out) {
    __shared__ unsigned As[2][GBM][AS_STRIDE];   // 20.5 KB
    __shared__ unsigned Bs[2][GBK][BS_STRIDE];   // 17.4 KB

    int tid  = threadIdx.x;
    int warp = tid >> 5;
    int lane = tid & 31;
    int grp  = lane >> 2;
    int kq   = lane & 3;
    int bm = blockIdx.y * GBM;
    int bn = blockIdx.x * GBN;
    int wm = (warp & 3) * 32;     // 4 warps along M
    int wn = (warp >> 2) * 64;    // 2 warps along N

    // Load mappings
    int a_row = tid >> 2;              // 0..63 (+64 on 2nd step)
    int a_c4  = (tid & 3) << 2;        // 0,4,8,12
    int b_row = tid >> 5;              // 0..7 (+8 on 2nd step)
    int b_c4  = (tid & 31) << 2;       // 0..124

    float c[2][8][4];
#pragma unroll
    for (int mt = 0; mt < 2; mt++)
#pragma unroll
        for (int nt = 0; nt < 8; nt++)
#pragma unroll
            for (int r = 0; r < 4; r++) c[mt][nt][r] = 0.f;

    // Prologue: load tile 0 into buffer 0
    float4 a4[2], b4[2];
#pragma unroll
    for (int r = 0; r < 2; r++) {
        int row = a_row + 64 * r;
        a4[r] = make_float4(0.f, 0.f, 0.f, 0.f);
        if (bm + row < N_NODES)
            a4[r] = *(const float4*)(g_agg + (size_t)(bm + row) * IN_CH + a_c4);
        b4[r] = *(const float4*)(W + (size_t)(b_row + 8 * r) * OUT_CH + bn + b_c4);
    }
#pragma unroll
    for (int r = 0; r < 2; r++) {
        int row = a_row + 64 * r;
        As[0][row][a_c4 + 0] = f2tf32(a4[r].x);
        As[0][row][a_c4 + 1] = f2tf32(a4[r].y);
        As[0][row][a_c4 + 2] = f2tf32(a4[r].z);
        As[0][row][a_c4 + 3] = f2tf32(a4[r].w);
        int brow = b_row + 8 * r;
        Bs[0][brow][b_c4 + 0] = f2tf32(b4[r].x);
        Bs[0][brow][b_c4 + 1] = f2tf32(b4[r].y);
        Bs[0][brow][b_c4 + 2] = f2tf32(b4[r].z);
        Bs[0][brow][b_c4 + 3] = f2tf32(b4[r].w);
    }
    __syncthreads();

    for (int it = 0; it < NKIT; it++) {
        int cur = it & 1;
        // Issue next tile's global loads before compute (latency overlap)
        if (it + 1 < NKIT) {
            int k0 = (it + 1) * GBK;
#pragma unroll
            for (int r = 0; r < 2; r++) {
                int row = a_row + 64 * r;
                a4[r] = make_float4(0.f, 0.f, 0.f, 0.f);
                if (bm + row < N_NODES)
                    a4[r] = *(const float4*)(g_agg + (size_t)(bm + row) * IN_CH + k0 + a_c4);
                b4[r] = *(const float4*)(W + (size_t)(k0 + b_row + 8 * r) * OUT_CH + bn + b_c4);
            }
        }

        // Compute on current buffer: kk = 0, 8
#pragma unroll
        for (int kk = 0; kk < GBK; kk += 8) {
            unsigned a[2][4], bf[8][2];
#pragma unroll
            for (int mt = 0; mt < 2; mt++) {
                int r0 = wm + mt * 16 + grp;
                a[mt][0] = As[cur][r0][kk + kq];
                a[mt][1] = As[cur][r0 + 8][kk + kq];
                a[mt][2] = As[cur][r0][kk + kq + 4];
                a[mt][3] = As[cur][r0 + 8][kk + kq + 4];
            }
#pragma unroll
            for (int nt = 0; nt < 8; nt++) {
                int n0 = wn + nt * 8 + grp;
                bf[nt][0] = Bs[cur][kk + kq][n0];
                bf[nt][1] = Bs[cur][kk + kq + 4][n0];
            }
#pragma unroll
            for (int mt = 0; mt < 2; mt++)
#pragma unroll
                for (int nt = 0; nt < 8; nt++) {
                    asm volatile(
                        "mma.sync.aligned.m16n8k8.row.col.f32.tf32.tf32.f32 "
                        "{%0,%1,%2,%3}, {%4,%5,%6,%7}, {%8,%9}, {%0,%1,%2,%3};"
                        : "+f"(c[mt][nt][0]), "+f"(c[mt][nt][1]),
                          "+f"(c[mt][nt][2]), "+f"(c[mt][nt][3])
                        : "r"(a[mt][0]), "r"(a[mt][1]), "r"(a[mt][2]), "r"(a[mt][3]),
                          "r"(bf[nt][0]), "r"(bf[nt][1]));
                }
        }

        // Store next tile into the other buffer
        if (it + 1 < NKIT) {
            int nxt = 1 - cur;
#pragma unroll
            for (int r = 0; r < 2; r++) {
                int row = a_row + 64 * r;
                As[nxt][row][a_c4 + 0] = f2tf32(a4[r].x);
                As[nxt][row][a_c4 + 1] = f2tf32(a4[r].y);
                As[nxt][row][a_c4 + 2] = f2tf32(a4[r].z);
                As[nxt][row][a_c4 + 3] = f2tf32(a4[r].w);
                int brow = b_row + 8 * r;
                Bs[nxt][brow][b_c4 + 0] = f2tf32(b4[r].x);
                Bs[nxt][brow][b_c4 + 1] = f2tf32(b4[r].y);
                Bs[nxt][brow][b_c4 + 2] = f2tf32(b4[r].z);
                Bs[nxt][brow][b_c4 + 3] = f2tf32(b4[r].w);
            }
        }
        __syncthreads();
    }

#pragma unroll
    for (int mt = 0; mt < 2; mt++) {
#pragma unroll
        for (int nt = 0; nt < 8; nt++) {
            int row0 = bm + wm + mt * 16 + grp;
            int col0 = bn + wn + nt * 8 + kq * 2;
            float2 bb = *(const float2*)(bias + col0);
            if (row0 < N_NODES) {
                float2 o = make_float2(c[mt][nt][0] + bb.x, c[mt][nt][1] + bb.y);
                *(float2*)(out + (size_t)row0 * OUT_CH + col0) = o;
            }
            if (row0 + 8 < N_NODES) {
                float2 o = make_float2(c[mt][nt][2] + bb.x, c[mt][nt][3] + bb.y);
                *(float2*)(out + (size_t)(row0 + 8) * OUT_CH + col0) = o;
            }
        }
    }
}

// ---------------------------------------------------------------------------
extern "C" void kernel_launch(void* const* d_in, const int* in_sizes, int n_in,
                              void* d_out, int out_size) {
    const float* x  = (const float*)d_in[0];
    const float* W  = (const float*)d_in[1];
    const float* b  = (const float*)d_in[2];
    const int*   ei = (const int*)d_in[3];     // int32 (JAX x64 disabled)
    const float* ew = (const float*)d_in[4];
    float* out = (float*)d_out;

    k_init<<<(N_NODES + 255) / 256, 256>>>();
    k_edge_deg<<<(N_EDGES + 255) / 256, 256>>>(ei, ew);
    k_scan_a<<<NSB, SB>>>();
    k_scan_bc<<<NSB, SB>>>();
    k_fill<<<(N_EDGES + 255) / 256, 256>>>(ei);
    k_aggregate<<<(N_NODES * 32 + 255) / 256, 256>>>(x);

    dim3 g(OUT_CH / GBN, (N_NODES + GBM - 1) / GBM);
    k_gemm_tf32<<<g, 256>>>(W, b, out);
}